// round 5
// baseline (speedup 1.0000x reference)
#include <cuda_runtime.h>

// ROIAlign / crop_and_resize (bilinear, extrapolation_value = 0)
// feature_map: [8, 64, 64, 256] f32 (B,H,W,C), rois: [8,128,4] f32
// out: [1024, 14, 14, 256] f32
//
// One warp per (roi, output-row, channel-half). Walks the 14 output columns
// carrying the current left/right source-column registers; when the next
// pixel's source column matches a held one (warp-uniform integer test), the
// gather is skipped entirely — cuts L1 gather bytes ~30-40%.

#define B 8
#define H 64
#define W 64
#define C 256
#define NUM_ROIS 128
#define N_TOTAL (B * NUM_ROIS)          // 1024
#define CROP 14
#define TASKS (N_TOTAL * CROP * 2)      // 28672  (roi, row, half)
#define WARPS_PER_BLOCK 8

__global__ __launch_bounds__(256, 5) void roialign_kernel(
    const float* __restrict__ fm,
    const float* __restrict__ rois,
    float* __restrict__ out)
{
    const int lane = threadIdx.x & 31;
    const int wid  = threadIdx.x >> 5;
    const int task = blockIdx.x * WARPS_PER_BLOCK + wid;

    const int n    = task / (CROP * 2);        // roi
    const int rem  = task - n * (CROP * 2);
    const int i    = rem >> 1;                 // output row
    const int half = rem & 1;                  // channel half (0 / 128)
    const int b    = n >> 7;

    // ROI coords (warp-broadcast 16B load)
    const float4 r = __ldg((const float4*)(rois + n * 4));
    const float y1 = r.x, x1 = r.y, y2 = r.z, x2 = r.w;

    const float h_scale = (y2 - y1) * (float)(H - 1) / (float)(CROP - 1);
    const float w_scale = (x2 - x1) * (float)(W - 1) / (float)(CROP - 1);

    // y params (hoisted for the row)
    const float in_y = fmaf((float)i, h_scale, y1 * (float)(H - 1));
    const bool  vy   = (in_y >= 0.f) && (in_y <= (float)(H - 1));
    const float fy   = floorf(in_y);
    const float yl   = in_y - fy;
    const float omyl = 1.f - yl;
    const int ty = min(max((int)fy, 0), H - 1);
    const int by = min(max((int)ceilf(in_y), 0), H - 1);

    const int coff = half * 128 + lane * 4;
    const size_t base = (size_t)b * (H * W * C);
    const float* rowT = fm + base + (size_t)ty * (W * C) + coff;
    const float* rowB = fm + base + (size_t)by * (W * C) + coff;

    const float x0 = x1 * (float)(W - 1);
    float* op = out + (size_t)(n * (CROP * CROP) + i * CROP) * C + coff;

    // Held source-column registers (top & bottom row cells) and their indices
    int cl = -1, cr = -1;
    float4 Lt = make_float4(0.f, 0.f, 0.f, 0.f), Lb = Lt, Rt = Lt, Rb = Lt;

    #pragma unroll 1
    for (int j = 0; j < CROP; j++) {
        const float in_x = fmaf((float)j, w_scale, x0);
        const bool  v    = vy && (in_x >= 0.f) && (in_x <= (float)(W - 1));
        const float fx   = floorf(in_x);
        const float xl   = in_x - fx;
        const int lx = min(max((int)fx, 0), W - 1);
        const int rx = min(max((int)ceilf(in_x), 0), W - 1);

        float wtl = (1.f - xl) * omyl;
        float wtr = xl * omyl;
        float wbl = (1.f - xl) * yl;
        float wbr = xl * yl;
        if (!v) { wtl = wtr = wbl = wbr = 0.f; }

        // Left column: reuse held registers when the index matches (uniform)
        float4 nLt, nLb, nRt, nRb;
        if (lx == cl)        { nLt = Lt; nLb = Lb; }
        else if (lx == cr)   { nLt = Rt; nLb = Rb; }
        else {
            nLt = __ldg((const float4*)(rowT + lx * C));
            nLb = __ldg((const float4*)(rowB + lx * C));
        }
        // Right column
        if (rx == lx)        { nRt = nLt; nRb = nLb; }
        else if (rx == cr)   { nRt = Rt;  nRb = Rb; }
        else if (rx == cl)   { nRt = Lt;  nRb = Lb; }
        else {
            nRt = __ldg((const float4*)(rowT + rx * C));
            nRb = __ldg((const float4*)(rowB + rx * C));
        }

        Lt = nLt; Lb = nLb; Rt = nRt; Rb = nRb;
        cl = lx;  cr = rx;

        float4 o;
        o.x = fmaf(Lt.x, wtl, fmaf(Rt.x, wtr, fmaf(Lb.x, wbl, Rb.x * wbr)));
        o.y = fmaf(Lt.y, wtl, fmaf(Rt.y, wtr, fmaf(Lb.y, wbl, Rb.y * wbr)));
        o.z = fmaf(Lt.z, wtl, fmaf(Rt.z, wtr, fmaf(Lb.z, wbl, Rb.z * wbr)));
        o.w = fmaf(Lt.w, wtl, fmaf(Rt.w, wtr, fmaf(Lb.w, wbl, Rb.w * wbr)));

        __stcs((float4*)op, o);
        op += C;
    }
}

extern "C" void kernel_launch(void* const* d_in, const int* in_sizes, int n_in,
                              void* d_out, int out_size)
{
    const float* fm   = (const float*)d_in[0];
    const float* rois = (const float*)d_in[1];
    float* out = (float*)d_out;

    roialign_kernel<<<TASKS / WARPS_PER_BLOCK, 256>>>(fm, rois, out);
}